// round 10
// baseline (speedup 1.0000x reference)
#include <cuda_runtime.h>

#define WIDTH  512
#define HEIGHT 512
#define ROWS   32
#define TPB    128

#define W0d 0.30780133
#define W1d 0.38439734
#define C1f 1.0e-4f
#define C2f 9.0e-4f

#define WCf ((float)(W1d / W0d))                  // w (horizontal, scalar imm)
#define KKf ((float)(W0d * W0d))                  // k
#define K2f ((float)(W0d * W0d * W0d * W0d))      // k^2
#define TK2f ((float)(2.0 * W0d * W0d * W0d * W0d)) // 2k^2
#define TKf ((float)(2.0 * W0d * W0d))            // 2k

typedef unsigned long long u64;

__device__ double       g_acc   = 0.0;
__device__ unsigned int g_count = 0u;

__device__ __forceinline__ float frcp(float x) {
    float r; asm("rcp.approx.f32 %0, %1;" : "=f"(r) : "f"(x)); return r;
}

// ---- f32x2 helpers ----
__device__ __forceinline__ u64 pk(float lo, float hi) {
    u64 r; asm("mov.b64 %0, {%1, %2};" : "=l"(r) : "f"(lo), "f"(hi)); return r;
}
__device__ __forceinline__ void upk(float& lo, float& hi, u64 p) {
    asm("mov.b64 {%0, %1}, %2;" : "=f"(lo), "=f"(hi) : "l"(p));
}
__device__ __forceinline__ u64 mul2(u64 a, u64 b) {
    u64 r; asm("mul.rn.f32x2 %0, %1, %2;" : "=l"(r) : "l"(a), "l"(b)); return r;
}
__device__ __forceinline__ u64 add2(u64 a, u64 b) {
    u64 r; asm("add.rn.f32x2 %0, %1, %2;" : "=l"(r) : "l"(a), "l"(b)); return r;
}
__device__ __forceinline__ u64 sub2(u64 a, u64 b) {
    u64 r; asm("sub.rn.f32x2 %0, %1, %2;" : "=l"(r) : "l"(a), "l"(b)); return r;
}
__device__ __forceinline__ u64 fma2(u64 a, u64 b, u64 c) {
    u64 r; asm("fma.rn.f32x2 %0, %1, %2, %3;" : "=l"(r) : "l"(a), "l"(b), "l"(c)); return r;
}
__device__ __forceinline__ u64 cpk(float c) {
    unsigned u = __float_as_uint(c); return ((u64)u << 32) | u;
}

// prefetched row data; ea/eb: left halo (lane0) or right halo (lane31)
struct Ld {
    float4 a4, b4;
    float  ea, eb;
};

__device__ __forceinline__ Ld load_row(const float* __restrict__ pa,
                                       const float* __restrict__ pb,
                                       int x0, int lane) {
    Ld L;
    L.a4 = *reinterpret_cast<const float4*>(pa + x0);
    L.b4 = *reinterpret_cast<const float4*>(pb + x0);
    const int  ex    = (lane == 0) ? (x0 - 1) : (x0 + 4);
    const bool valid = (lane == 0) ? (x0 > 0)
                                   : (lane == 31 && x0 + 4 < WIDTH);
    L.ea = valid ? pa[ex] : 0.f;
    L.eb = valid ? pb[ex] : 0.f;
    return L;
}

// Unnormalized horizontal 3-tap sums -> 10 packed pairs.
// Hp[q*2+p]: quantity q in {a,b,aa,bb,ab}, pixel-pair p in {01, 23}.
__device__ __forceinline__ void compute_h(const Ld& L, int lane,
                                          u64* __restrict__ Hp) {
    float la = __shfl_up_sync(0xffffffffu, L.a4.w, 1);
    float ra = __shfl_down_sync(0xffffffffu, L.a4.x, 1);
    float lb = __shfl_up_sync(0xffffffffu, L.b4.w, 1);
    float rb = __shfl_down_sync(0xffffffffu, L.b4.x, 1);
    if (lane == 0)  { la = L.ea; lb = L.eb; }
    if (lane == 31) { ra = L.ea; rb = L.eb; }

    float va[6] = { la, L.a4.x, L.a4.y, L.a4.z, L.a4.w, ra };
    float vb[6] = { lb, L.b4.x, L.b4.y, L.b4.z, L.b4.w, rb };

    {
        float h0 = fmaf(WCf, va[1], va[0] + va[2]);
        float h1 = fmaf(WCf, va[2], va[1] + va[3]);
        float h2 = fmaf(WCf, va[3], va[2] + va[4]);
        float h3 = fmaf(WCf, va[4], va[3] + va[5]);
        Hp[0] = pk(h0, h1); Hp[1] = pk(h2, h3);
        h0 = fmaf(WCf, vb[1], vb[0] + vb[2]);
        h1 = fmaf(WCf, vb[2], vb[1] + vb[3]);
        h2 = fmaf(WCf, vb[3], vb[2] + vb[4]);
        h3 = fmaf(WCf, vb[4], vb[3] + vb[5]);
        Hp[2] = pk(h0, h1); Hp[3] = pk(h2, h3);
    }
    {
        float p[6];
#pragma unroll
        for (int j = 0; j < 6; ++j) p[j] = va[j] * va[j];
        Hp[4] = pk(fmaf(WCf, p[1], p[0] + p[2]), fmaf(WCf, p[2], p[1] + p[3]));
        Hp[5] = pk(fmaf(WCf, p[3], p[2] + p[4]), fmaf(WCf, p[4], p[3] + p[5]));
#pragma unroll
        for (int j = 0; j < 6; ++j) p[j] = vb[j] * vb[j];
        Hp[6] = pk(fmaf(WCf, p[1], p[0] + p[2]), fmaf(WCf, p[2], p[1] + p[3]));
        Hp[7] = pk(fmaf(WCf, p[3], p[2] + p[4]), fmaf(WCf, p[4], p[3] + p[5]));
#pragma unroll
        for (int j = 0; j < 6; ++j) p[j] = va[j] * vb[j];
        Hp[8] = pk(fmaf(WCf, p[1], p[0] + p[2]), fmaf(WCf, p[2], p[1] + p[3]));
        Hp[9] = pk(fmaf(WCf, p[3], p[2] + p[4]), fmaf(WCf, p[4], p[3] + p[5]));
    }
}

// packed constants (per-thread, hoisted)
struct Cst { u64 wc, kk, k2, tk2, tk, c1, c2; };

// emit 4 px (2 pairs): V = P + Hn, then SSIM map, packed
__device__ __forceinline__ void emit4(const u64* __restrict__ P,
                                      const u64* __restrict__ Hn,
                                      const Cst& K, float& acc) {
#pragma unroll
    for (int p = 0; p < 2; ++p) {
        u64 U1  = add2(P[0 + p], Hn[0 + p]);
        u64 U2  = add2(P[2 + p], Hn[2 + p]);
        u64 S11 = add2(P[4 + p], Hn[4 + p]);
        u64 S22 = add2(P[6 + p], Hn[6 + p]);
        u64 S12 = add2(P[8 + p], Hn[8 + p]);

        u64 m11 = mul2(U1, U1);
        u64 m22 = mul2(U2, U2);
        u64 m12 = mul2(U1, U2);
        u64 msum = add2(m11, m22);
        u64 ssum = add2(S11, S22);

        u64 n1 = fma2(K.tk2, m12, K.c1);                       // 2k^2 m12 + C1
        u64 t  = sub2(S12, mul2(K.kk, m12));                   // S12 - k m12
        u64 n2 = fma2(K.tk, t, K.c2);                          // 2k t + C2
        u64 d1 = fma2(K.k2, msum, K.c1);                       // k^2 msum + C1
        u64 u  = sub2(ssum, mul2(K.kk, msum));                 // ssum - k msum
        u64 d2 = fma2(K.kk, u, K.c2);                          // k u + C2

        u64 num = mul2(n1, n2);
        u64 den = mul2(d1, d2);
        float nlo, nhi, dlo, dhi;
        upk(nlo, nhi, num);
        upk(dlo, dhi, den);
        acc = fmaf(nlo, frcp(dlo), acc);
        acc = fmaf(nhi, frcp(dhi), acc);
    }
}

// P = Hprev + wc * Hcur (partial for the NEXT output row), packed
__device__ __forceinline__ void mkP(u64* __restrict__ P,
                                    const u64* __restrict__ Hprev,
                                    const u64* __restrict__ Hcur,
                                    const Cst& K) {
#pragma unroll
    for (int i = 0; i < 10; ++i) P[i] = fma2(K.wc, Hcur[i], Hprev[i]);
}

__global__ void __launch_bounds__(TPB, 6)
k_ssim(const float* __restrict__ A, const float* __restrict__ B,
       float* __restrict__ out, int nblocks) {
    const int plane = blockIdx.y;
    const int y0    = blockIdx.x * ROWS;
    const float* pa = A + plane * (WIDTH * HEIGHT) + y0 * WIDTH;
    const float* pb = B + plane * (WIDTH * HEIGHT) + y0 * WIDTH;

    const int t    = threadIdx.x;
    const int lane = t & 31;
    const int x0   = t << 2;

    Cst K;
    K.wc = cpk(WCf); K.kk = cpk(KKf); K.k2 = cpk(K2f);
    K.tk2 = cpk(TK2f); K.tk = cpk(TKf); K.c1 = cpk(C1f); K.c2 = cpk(C2f);

    u64 P[10], H0[10], H1[10];
    float acc = 0.f;
    Ld n0, n1;

    // H(y0-1) -> H0 (zero above image for top strip)
    if (y0 > 0) {
        n0 = load_row(pa - WIDTH, pb - WIDTH, x0, lane);
        compute_h(n0, lane, H0);
    } else {
#pragma unroll
        for (int i = 0; i < 10; ++i) H0[i] = 0ull;
    }

    // row y0 -> H1; prefetch row y0+1
    n1 = load_row(pa, pb, x0, lane);
    n0 = load_row(pa + WIDTH, pb + WIDTH, x0, lane);
    compute_h(n1, lane, H1);
    mkP(P, H0, H1, K);                // partial for output row y0

    pa += 2 * WIDTH; pb += 2 * WIDTH; // point at row y0+2

    // rows y0+1 .. y0+30: 15 double-iterations, prefetch one row ahead
#pragma unroll 1
    for (int it = 0; it < 15; ++it) {
        n1 = load_row(pa, pb, x0, lane);                  // row y0+2+2it
        compute_h(n0, lane, H0);                          // row y0+1+2it
        emit4(P, H0, K, acc);                             // emit row y0+2it
        mkP(P, H1, H0, K);

        n0 = load_row(pa + WIDTH, pb + WIDTH, x0, lane);  // row y0+3+2it
        compute_h(n1, lane, H1);                          // row y0+2+2it
        emit4(P, H1, K, acc);                             // emit row y0+1+2it
        mkP(P, H0, H1, K);

        pa += 2 * WIDTH; pb += 2 * WIDTH;
    }
    // pa/pb now point at row y0+32

    // row y0+31 (already prefetched in n0)
    compute_h(n0, lane, H0);
    emit4(P, H0, K, acc);                                 // emit row y0+30
    mkP(P, H1, H0, K);

    // row y0+32 (zero below image for bottom strip)
    if (y0 + ROWS < HEIGHT) {
        n1 = load_row(pa, pb, x0, lane);
        compute_h(n1, lane, H1);
    } else {
#pragma unroll
        for (int i = 0; i < 10; ++i) H1[i] = 0ull;
    }
    emit4(P, H1, K, acc);                                 // emit row y0+31

    // reduction: warp shuffle, then cross-warp via smem
    __shared__ float red[4];
#pragma unroll
    for (int off = 16; off > 0; off >>= 1)
        acc += __shfl_down_sync(0xffffffffu, acc, off);
    if (lane == 0) red[t >> 5] = acc;
    __syncthreads();

    if (t == 0) {
        float s = red[0] + red[1] + red[2] + red[3];
        atomicAdd(&g_acc, (double)s);
        __threadfence();
        unsigned prev = atomicAdd(&g_count, 1u);
        if (prev == (unsigned)(nblocks - 1)) {
            double tot = atomicAdd(&g_acc, 0.0);   // serialized fresh read
            out[0] = (float)(1.0 - tot);
            g_acc   = 0.0;                         // reset for next replay
            __threadfence();
            g_count = 0u;
        }
    }
}

extern "C" void kernel_launch(void* const* d_in, const int* in_sizes, int n_in,
                              void* d_out, int out_size) {
    const float* A = (const float*)d_in[0];
    const float* B = (const float*)d_in[1];
    float* out = (float*)d_out;

    const int planes = in_sizes[0] / (WIDTH * HEIGHT);   // 96
    dim3 grid(HEIGHT / ROWS, planes);                    // 16 x 96 = 1536
    k_ssim<<<grid, TPB>>>(A, B, out, grid.x * planes);
}

// round 11
// speedup vs baseline: 1.3417x; 1.3417x over previous
#include <cuda_runtime.h>

#define WIDTH  512
#define HEIGHT 512
#define ROWS   32
#define TPB    128

#define W0d 0.30780133
#define W1d 0.38439734
#define C1f 1.0e-4f
#define C2f 9.0e-4f

// compile-time constants -> FFMA immediate operands
#define WCf   ((float)(W1d / W0d))                         // w
#define KKf   ((float)(W0d * W0d))                         // k
#define K2f   ((float)(W0d * W0d * W0d * W0d))             // k^2
#define NK2f  ((float)(-(W0d * W0d * W0d * W0d)))          // -k^2
#define TK2f  ((float)( 2.0 * W0d * W0d * W0d * W0d))      // 2k^2
#define NTK2f ((float)(-2.0 * W0d * W0d * W0d * W0d))      // -2k^2
#define TKf   ((float)( 2.0 * W0d * W0d))                  // 2k

__device__ double       g_acc   = 0.0;
__device__ unsigned int g_count = 0u;

__device__ __forceinline__ float frcp(float x) {
    float r; asm("rcp.approx.f32 %0, %1;" : "=f"(r) : "f"(x)); return r;
}

// prefetched row data; ea/eb: left halo (lane0) or right halo (lane31)
struct Ld {
    float4 a4, b4;
    float  ea, eb;
};

__device__ __forceinline__ Ld load_row(const float* __restrict__ pa,
                                       const float* __restrict__ pb,
                                       int x0, int exoff, bool evalid) {
    Ld L;
    L.a4 = *reinterpret_cast<const float4*>(pa + x0);
    L.b4 = *reinterpret_cast<const float4*>(pb + x0);
    L.ea = evalid ? pa[exoff] : 0.f;
    L.eb = evalid ? pb[exoff] : 0.f;
    return L;
}

// 4 channels: H[ch*4+i], ch in {a, b, s=aa+bb, ab} -> 16 floats
__device__ __forceinline__ void compute_h(const Ld& L, int lane,
                                          float* __restrict__ H) {
    float la = __shfl_up_sync(0xffffffffu, L.a4.w, 1);
    float ra = __shfl_down_sync(0xffffffffu, L.a4.x, 1);
    float lb = __shfl_up_sync(0xffffffffu, L.b4.w, 1);
    float rb = __shfl_down_sync(0xffffffffu, L.b4.x, 1);
    if (lane == 0)  { la = L.ea; lb = L.eb; }
    if (lane == 31) { ra = L.ea; rb = L.eb; }

    float va[6] = { la, L.a4.x, L.a4.y, L.a4.z, L.a4.w, ra };
    float vb[6] = { lb, L.b4.x, L.b4.y, L.b4.z, L.b4.w, rb };

#pragma unroll
    for (int i = 0; i < 4; ++i) {
        H[0 + i] = fmaf(WCf, va[i + 1], va[i] + va[i + 2]);
        H[4 + i] = fmaf(WCf, vb[i + 1], vb[i] + vb[i + 2]);
    }
    {
        float p[6];
#pragma unroll
        for (int j = 0; j < 6; ++j) p[j] = fmaf(vb[j], vb[j], va[j] * va[j]);
#pragma unroll
        for (int i = 0; i < 4; ++i)
            H[8 + i] = fmaf(WCf, p[i + 1], p[i] + p[i + 2]);
#pragma unroll
        for (int j = 0; j < 6; ++j) p[j] = va[j] * vb[j];
#pragma unroll
        for (int i = 0; i < 4; ++i)
            H[12 + i] = fmaf(WCf, p[i + 1], p[i] + p[i + 2]);
    }
}

// emit 4 px: V = P + Hn (full unnormalized separable conv), SSIM map
__device__ __forceinline__ void emit4(const float* __restrict__ P,
                                      const float* __restrict__ Hn,
                                      float& acc) {
#pragma unroll
    for (int i = 0; i < 4; ++i) {
        float U1  = P[ 0 + i] + Hn[ 0 + i];
        float U2  = P[ 4 + i] + Hn[ 4 + i];
        float Vs  = P[ 8 + i] + Hn[ 8 + i];     // conv(a^2 + b^2)
        float S12 = P[12 + i] + Hn[12 + i];

        float m12  = U1 * U2;
        float msum = fmaf(U2, U2, U1 * U1);

        float n1 = fmaf(TK2f, m12, C1f);                    // 2k^2 m12 + C1
        float n2 = fmaf(TKf, S12, fmaf(NTK2f, m12, C2f));   // 2k S12 - 2k^2 m12 + C2
        float d1 = fmaf(K2f, msum, C1f);                    // k^2 msum + C1
        float d2 = fmaf(KKf, Vs, fmaf(NK2f, msum, C2f));    // k Vs - k^2 msum + C2

        acc = fmaf(n1 * n2, frcp(d1 * d2), acc);
    }
}

// P = Hprev + wc * Hcur (partial for the NEXT output row)
__device__ __forceinline__ void mkP(float* __restrict__ P,
                                    const float* __restrict__ Hprev,
                                    const float* __restrict__ Hcur) {
#pragma unroll
    for (int i = 0; i < 16; ++i) P[i] = fmaf(WCf, Hcur[i], Hprev[i]);
}

__global__ void __launch_bounds__(TPB, 6)
k_ssim(const float* __restrict__ A, const float* __restrict__ B,
       float* __restrict__ out, int nblocks) {
    const int plane = blockIdx.y;
    const int y0    = blockIdx.x * ROWS;
    const float* pa = A + plane * (WIDTH * HEIGHT) + y0 * WIDTH;
    const float* pb = B + plane * (WIDTH * HEIGHT) + y0 * WIDTH;

    const int t    = threadIdx.x;
    const int lane = t & 31;
    const int x0   = t << 2;

    // hoisted edge-load parameters (thread-invariant)
    const int  exoff  = (lane == 0) ? (x0 - 1) : (x0 + 4);
    const bool evalid = (lane == 0) ? (x0 > 0)
                                    : (lane == 31 && x0 + 4 < WIDTH);

    float P[16], H0[16], H1[16];
    float acc = 0.f;
    Ld n0, n1;

    // H(y0-1) -> H0 (zero above image for top strip)
    if (y0 > 0) {
        n0 = load_row(pa - WIDTH, pb - WIDTH, x0, exoff, evalid);
        compute_h(n0, lane, H0);
    } else {
#pragma unroll
        for (int i = 0; i < 16; ++i) H0[i] = 0.f;
    }

    // row y0 -> H1; prefetch row y0+1
    n1 = load_row(pa, pb, x0, exoff, evalid);
    n0 = load_row(pa + WIDTH, pb + WIDTH, x0, exoff, evalid);
    compute_h(n1, lane, H1);
    mkP(P, H0, H1);                   // partial for output row y0

    pa += 2 * WIDTH; pb += 2 * WIDTH; // point at row y0+2

    // rows y0+1 .. y0+30: 15 double-iterations, prefetch one row ahead
#pragma unroll 1
    for (int it = 0; it < 15; ++it) {
        n1 = load_row(pa, pb, x0, exoff, evalid);                 // y0+2+2it
        compute_h(n0, lane, H0);                                  // y0+1+2it
        emit4(P, H0, acc);                                        // emit y0+2it
        mkP(P, H1, H0);

        n0 = load_row(pa + WIDTH, pb + WIDTH, x0, exoff, evalid); // y0+3+2it
        compute_h(n1, lane, H1);                                  // y0+2+2it
        emit4(P, H1, acc);                                        // emit y0+1+2it
        mkP(P, H0, H1);

        pa += 2 * WIDTH; pb += 2 * WIDTH;
    }
    // pa/pb now point at row y0+32

    // row y0+31 (already prefetched in n0)
    compute_h(n0, lane, H0);
    emit4(P, H0, acc);                                            // emit y0+30
    mkP(P, H1, H0);

    // row y0+32 (zero below image for bottom strip)
    if (y0 + ROWS < HEIGHT) {
        n1 = load_row(pa, pb, x0, exoff, evalid);
        compute_h(n1, lane, H1);
    } else {
#pragma unroll
        for (int i = 0; i < 16; ++i) H1[i] = 0.f;
    }
    emit4(P, H1, acc);                                            // emit y0+31

    // reduction: warp shuffle, then cross-warp via smem
    __shared__ float red[4];
#pragma unroll
    for (int off = 16; off > 0; off >>= 1)
        acc += __shfl_down_sync(0xffffffffu, acc, off);
    if (lane == 0) red[t >> 5] = acc;
    __syncthreads();

    if (t == 0) {
        float s = red[0] + red[1] + red[2] + red[3];
        atomicAdd(&g_acc, (double)s);
        __threadfence();
        unsigned prev = atomicAdd(&g_count, 1u);
        if (prev == (unsigned)(nblocks - 1)) {
            double tot = atomicAdd(&g_acc, 0.0);   // serialized fresh read
            out[0] = (float)(1.0 - tot);
            g_acc   = 0.0;                         // reset for next replay
            __threadfence();
            g_count = 0u;
        }
    }
}

extern "C" void kernel_launch(void* const* d_in, const int* in_sizes, int n_in,
                              void* d_out, int out_size) {
    const float* A = (const float*)d_in[0];
    const float* B = (const float*)d_in[1];
    float* out = (float*)d_out;

    const int planes = in_sizes[0] / (WIDTH * HEIGHT);   // 96
    dim3 grid(HEIGHT / ROWS, planes);                    // 16 x 96 = 1536
    k_ssim<<<grid, TPB>>>(A, B, out, grid.x * planes);
}